// round 13
// baseline (speedup 1.0000x reference)
#include <cuda_runtime.h>
#include <cuda_bf16.h>
#include <cuda_fp16.h>
#include <math.h>
#include <stdint.h>

#define BATCH 8
#define SEQ   2048
#define EMBED 1024
#define HEAD  64
#define MROWS (BATCH * SEQ)          // 16384

// Projected q,k,v in fp16. q: single (pre-scaled by log2(e)/32). k,v: hi/lo.
__device__ __half g_qh[MROWS * HEAD];
__device__ __half g_kh[MROWS * HEAD];
__device__ __half g_kl[MROWS * HEAD];
__device__ __half g_vh[MROWS * HEAD];
__device__ __half g_vl[MROWS * HEAD];

// W transposed (bf16 hi/lo; proj-internal): row = mat*64+n, col = k.
__device__ __nv_bfloat16 g_wth[192 * 1024];
__device__ __nv_bfloat16 g_wtl[192 * 1024];

// Split-K partial scratch: 16 heavy qb x 2 splits x 8 batches = 256 entries.
__device__ float g_po[256][64 * 64];
__device__ float g_pm[256][64];
__device__ float g_pl[256][64];

#define QSCALE 0.045084220027780106f   // log2(e) / 32

// ---------------------------------------------------------------------------
// Helpers
// ---------------------------------------------------------------------------
__device__ __forceinline__ uint32_t smem_u32(const void* p) {
    uint32_t a;
    asm("{ .reg .u64 t; cvta.to.shared.u64 t, %1; cvt.u32.u64 %0, t; }" : "=r"(a) : "l"(p));
    return a;
}
__device__ __forceinline__ void ldsm4(uint32_t* r, uint32_t a) {
    asm volatile("ldmatrix.sync.aligned.m8n8.x4.shared.b16 {%0,%1,%2,%3}, [%4];"
        : "=r"(r[0]), "=r"(r[1]), "=r"(r[2]), "=r"(r[3]) : "r"(a));
}
__device__ __forceinline__ void ldsm2(uint32_t* r, uint32_t a) {
    asm volatile("ldmatrix.sync.aligned.m8n8.x2.shared.b16 {%0,%1}, [%2];"
        : "=r"(r[0]), "=r"(r[1]) : "r"(a));
}
__device__ __forceinline__ void ldsm4t(uint32_t* r, uint32_t a) {
    asm volatile("ldmatrix.sync.aligned.m8n8.x4.trans.shared.b16 {%0,%1,%2,%3}, [%4];"
        : "=r"(r[0]), "=r"(r[1]), "=r"(r[2]), "=r"(r[3]) : "r"(a));
}
// bf16 mma (proj)
__device__ __forceinline__ void mma_bf(float* c, const uint32_t* a, const uint32_t* b) {
    asm volatile("mma.sync.aligned.m16n8k16.row.col.f32.bf16.bf16.f32 "
        "{%0,%1,%2,%3}, {%4,%5,%6,%7}, {%8,%9}, {%0,%1,%2,%3};"
        : "+f"(c[0]), "+f"(c[1]), "+f"(c[2]), "+f"(c[3])
        : "r"(a[0]), "r"(a[1]), "r"(a[2]), "r"(a[3]), "r"(b[0]), "r"(b[1]));
}
// fp16 mma (attn)
__device__ __forceinline__ void mma_h(float* c, const uint32_t* a, const uint32_t* b) {
    asm volatile("mma.sync.aligned.m16n8k16.row.col.f32.f16.f16.f32 "
        "{%0,%1,%2,%3}, {%4,%5,%6,%7}, {%8,%9}, {%0,%1,%2,%3};"
        : "+f"(c[0]), "+f"(c[1]), "+f"(c[2]), "+f"(c[3])
        : "r"(a[0]), "r"(a[1]), "r"(a[2]), "r"(a[3]), "r"(b[0]), "r"(b[1]));
}
__device__ __forceinline__ uint32_t f2bf2(float lo, float hi) {
    uint32_t r;
    asm("cvt.rn.bf16x2.f32 %0, %1, %2;" : "=r"(r) : "f"(hi), "f"(lo));
    return r;
}
__device__ __forceinline__ uint32_t f2h2(float lo, float hi) {
    uint32_t r;
    asm("cvt.rn.f16x2.f32 %0, %1, %2;" : "=r"(r) : "f"(hi), "f"(lo));
    return r;
}
__device__ __forceinline__ void split2(float v, float& hf, float& lf) {
    __nv_bfloat16 h = __float2bfloat16_rn(v);
    hf = __bfloat162float(h);
    lf = v - hf;
}
__device__ __forceinline__ void splitpackh(float v0, float v1, uint32_t& ph, uint32_t& pl) {
    __half h0 = __float2half_rn(v0), h1 = __float2half_rn(v1);
    float l0 = v0 - __half2float(h0), l1 = v1 - __half2float(h1);
    ph = (uint32_t)__half_as_ushort(h0) | ((uint32_t)__half_as_ushort(h1) << 16);
    pl = f2h2(l0, l1);
}
__device__ __forceinline__ float ex2(float x) {
    float r; asm("ex2.approx.ftz.f32 %0, %1;" : "=f"(r) : "f"(x)); return r;
}
__device__ __forceinline__ float qmax(float v) {
    v = fmaxf(v, __shfl_xor_sync(0xffffffffu, v, 1));
    v = fmaxf(v, __shfl_xor_sync(0xffffffffu, v, 2));
    return v;
}
__device__ __forceinline__ float qsum(float v) {
    v += __shfl_xor_sync(0xffffffffu, v, 1);
    v += __shfl_xor_sync(0xffffffffu, v, 2);
    return v;
}
__device__ __forceinline__ void cp16(uint32_t dst, const void* src) {
    asm volatile("cp.async.cg.shared.global [%0], [%1], 16;" :: "r"(dst), "l"(src));
}
#define CP_COMMIT() asm volatile("cp.async.commit_group;" ::: "memory")
#define CP_WAIT(n)  asm volatile("cp.async.wait_group %0;" :: "n"(n) : "memory")

#define PADB 144   // padded row pitch (bytes)

// ---------------------------------------------------------------------------
// Kernel 0: W prep (bf16 hi/lo, unchanged)
// ---------------------------------------------------------------------------
__global__ __launch_bounds__(256) void wprep_kernel(
    const float* __restrict__ Wq,
    const float* __restrict__ Wk,
    const float* __restrict__ Wv)
{
    int i = blockIdx.x * 256 + threadIdx.x;
    if (i >= 192 * 1024) return;
    int row = i >> 10;
    int k   = i & 1023;
    int mat = row >> 6;
    int n   = row & 63;
    const float* W = (mat == 0) ? Wq : ((mat == 1) ? Wk : Wv);
    float v = W[(size_t)k * HEAD + n];
    float hf, lf; split2(v, hf, lf);
    g_wth[i] = __float2bfloat16_rn(hf);
    g_wtl[i] = __float2bfloat16_rn(lf);
}

// ---------------------------------------------------------------------------
// Kernel 1: QKV projection (3-term bf16 internally; fp16 outputs)
// ---------------------------------------------------------------------------
#define PJ_XH  0
#define PJ_XL  18432
#define PJ_WH  36864
#define PJ_WL  64512
#define PJ_SMEM 92160

__global__ __launch_bounds__(256) void proj_kernel(const float* __restrict__ x)
{
    extern __shared__ char smem[];
    const uint32_t sb = smem_u32(smem);
    const int tid  = threadIdx.x;
    const int w    = tid >> 5;
    const int lane = tid & 31;
    const int r0   = (w >> 1) * 32;
    const int c0   = (w & 1) * 96;
    const int row0 = blockIdx.x * 128;

    float C[2][12][4];
#pragma unroll
    for (int mt = 0; mt < 2; mt++)
#pragma unroll
        for (int nt = 0; nt < 12; nt++)
#pragma unroll
            for (int e = 0; e < 4; e++) C[mt][nt][e] = 0.f;

    const int a_row = (lane & 7) + ((lane >> 3) & 1) * 8;
    const int a_c16 = ((lane >> 4) & 1) * 16;
    const int b_row = lane & 7;
    const int b_c16 = ((lane >> 3) & 1) * 16;

    for (int c = 0; c < 16; c++) {
        const int k0 = c * 64;
        for (int i = tid; i < 2048; i += 256) {
            int r = i >> 4, c4 = i & 15;
            float4 v = *(const float4*)&x[(size_t)(row0 + r) * EMBED + k0 + c4 * 4];
            float h0, l0, h1, l1, h2, l2, h3, l3;
            split2(v.x, h0, l0); split2(v.y, h1, l1);
            split2(v.z, h2, l2); split2(v.w, h3, l3);
            int off = r * PADB + c4 * 8;
            *(uint32_t*)(smem + PJ_XH + off)     = f2bf2(h0, h1);
            *(uint32_t*)(smem + PJ_XH + off + 4) = f2bf2(h2, h3);
            *(uint32_t*)(smem + PJ_XL + off)     = f2bf2(l0, l1);
            *(uint32_t*)(smem + PJ_XL + off + 4) = f2bf2(l2, l3);
        }
        for (int i = tid; i < 1536; i += 256) {
            int row = i >> 3, d8 = i & 7;
            size_t src = ((size_t)row * 1024 + k0) / 8 + d8;
            int off = row * PADB + d8 * 16;
            *(uint4*)(smem + PJ_WH + off) = ((const uint4*)g_wth)[src];
            *(uint4*)(smem + PJ_WL + off) = ((const uint4*)g_wtl)[src];
        }
        __syncthreads();

#pragma unroll
        for (int kt = 0; kt < 4; kt++) {
            uint32_t Ah[2][4], Al[2][4];
#pragma unroll
            for (int mt = 0; mt < 2; mt++) {
                uint32_t ao = (uint32_t)((r0 + mt * 16 + a_row) * PADB + kt * 32 + a_c16);
                ldsm4(Ah[mt], sb + PJ_XH + ao);
                ldsm4(Al[mt], sb + PJ_XL + ao);
            }
#pragma unroll
            for (int nt = 0; nt < 12; nt++) {
                uint32_t bo = (uint32_t)((c0 + nt * 8 + b_row) * PADB + kt * 32 + b_c16);
                uint32_t Bh[2], Bl[2];
                ldsm2(Bh, sb + PJ_WH + bo);
                ldsm2(Bl, sb + PJ_WL + bo);
#pragma unroll
                for (int mt = 0; mt < 2; mt++) {
                    mma_bf(C[mt][nt], Ah[mt], Bh);
                    mma_bf(C[mt][nt], Ah[mt], Bl);
                    mma_bf(C[mt][nt], Al[mt], Bh);
                }
            }
        }
        __syncthreads();
    }

#pragma unroll
    for (int mt = 0; mt < 2; mt++) {
#pragma unroll
        for (int nt = 0; nt < 12; nt++) {
            int col = c0 + nt * 8 + (lane & 3) * 2;
            int mat = col >> 6;
            int cc  = col & 63;
            int row_a = row0 + r0 + mt * 16 + (lane >> 2);
#pragma unroll
            for (int h = 0; h < 2; h++) {
                int row = row_a + h * 8;
                float v0 = C[mt][nt][2 * h], v1 = C[mt][nt][2 * h + 1];
                if (mat == 0) {
                    *(uint32_t*)&g_qh[(size_t)row * HEAD + cc] = f2h2(v0 * QSCALE, v1 * QSCALE);
                } else {
                    __half* gh = (mat == 1) ? g_kh : g_vh;
                    __half* gl = (mat == 1) ? g_kl : g_vl;
                    uint32_t ph, pl;
                    splitpackh(v0, v1, ph, pl);
                    *(uint32_t*)&gh[(size_t)row * HEAD + cc] = ph;
                    *(uint32_t*)&gl[(size_t)row * HEAD + cc] = pl;
                }
            }
        }
    }
}

// ---------------------------------------------------------------------------
// Kernel 2: causal flash attention, fp16 2-term, split-K balanced.
// CTA = 128 threads (4 warps), 64 q rows. Grid (48, 8):
//   x in [0,32): qb = 31 - (x>>1), heavy blocks split into 2 key-halves.
//   x in [32,48): qb = 47 - x (15..0), full range.
// Split CTAs write (O,m,l) partials to scratch; combine_kernel merges.
// ---------------------------------------------------------------------------
#define AT_QH   0
#define AT_BUF0 9216
#define AT_BUF1 46080
#define AT_KHO  0
#define AT_KLO  9216
#define AT_VHO  18432
#define AT_VLO  27648
#define AT_SMEM 82944

__global__ __launch_bounds__(128) void attn_kernel(float* __restrict__ out)
{
    extern __shared__ char smem[];
    const uint32_t sb = smem_u32(smem);
    const int tid  = threadIdx.x;
    const int w    = tid >> 5;
    const int lane = tid & 31;
    const int b    = blockIdx.y;
    const int x    = blockIdx.x;

    int qb, kt0, kt1, entry = -1;
    if (x < 32) {
        qb = 31 - (x >> 1);
        const int nt = qb + 1, h = nt >> 1;
        if (x & 1) { kt0 = 0; kt1 = h;  entry = ((b * 16 + (qb - 16)) << 1); }
        else       { kt0 = h; kt1 = nt; entry = ((b * 16 + (qb - 16)) << 1) | 1; }
    } else {
        qb = 47 - x;          // 15..0
        kt0 = 0; kt1 = qb + 1;
    }
    const int qbase = qb * 64;

    auto issue_tile = [&](int kt, int buf) {
        const size_t gb = ((size_t)b * SEQ + kt * 64) * HEAD;
        const uint32_t bufb = sb + (buf ? AT_BUF1 : AT_BUF0);
#pragma unroll
        for (int i = tid; i < 2048; i += 128) {
            int arr = i >> 9, rem = i & 511;
            int r = rem >> 3, d8 = rem & 7;
            const __half* src =
                (arr == 0) ? g_kh : ((arr == 1) ? g_kl : ((arr == 2) ? g_vh : g_vl));
            int aoff = (arr == 0) ? AT_KHO : ((arr == 1) ? AT_KLO : ((arr == 2) ? AT_VHO : AT_VLO));
            cp16(bufb + aoff + r * PADB + d8 * 16, src + gb + (size_t)r * HEAD + d8 * 8);
        }
        CP_COMMIT();
    };

    issue_tile(kt0, 0);

    // Q tile (64 x 64 fp16) -> smem -> hoisted register fragments
    {
        const uint4* qh = (const uint4*)(g_qh + ((size_t)b * SEQ + qbase) * HEAD);
        for (int i = tid; i < 512; i += 128) {
            int r = i >> 3, d8 = i & 7;
            *(uint4*)(smem + AT_QH + r * PADB + d8 * 16) = qh[i];
        }
    }
    __syncthreads();

    const int a_row = (lane & 7) + ((lane >> 3) & 1) * 8;
    const int a_c16 = ((lane >> 4) & 1) * 16;
    uint32_t QA[4][4];
#pragma unroll
    for (int k4 = 0; k4 < 4; k4++)
        ldsm4(QA[k4], sb + AT_QH + (uint32_t)((w * 16 + a_row) * PADB + k4 * 32 + a_c16));

    float O[8][4];
    float m_[2], l_[2];
#pragma unroll
    for (int nd = 0; nd < 8; nd++)
#pragma unroll
        for (int e = 0; e < 4; e++) O[nd][e] = 0.f;
    m_[0] = m_[1] = -1e30f;
    l_[0] = l_[1] = 0.f;

    const int bp_row = (lane & 7) + ((lane >> 4) & 1) * 32;
    const int bp_c16 = ((lane >> 3) & 1) * 16;
    const int vp_row = lane & 15;
    const int vp_c16 = ((lane >> 4) & 1) * 64;

    for (int kt = kt0; kt < kt1; kt++) {
        const int cur = (kt - kt0) & 1;
        if (kt + 1 < kt1) { issue_tile(kt + 1, 1 - cur); CP_WAIT(1); }
        else              { CP_WAIT(0); }
        __syncthreads();

        const uint32_t bufb = sb + (cur ? AT_BUF1 : AT_BUF0);

        // ---- S = Qh·Kh + Qh·Kl  (fp16 2-term) ----
        float S[8][4];
#pragma unroll
        for (int nt = 0; nt < 8; nt++)
#pragma unroll
            for (int e = 0; e < 4; e++) S[nt][e] = 0.f;

#pragma unroll
        for (int k4 = 0; k4 < 4; k4++) {
            uint32_t KH[8][2], KL[8][2];
#pragma unroll
            for (int nt = 0; nt < 4; nt++) {
                uint32_t bo = (uint32_t)((nt * 8 + bp_row) * PADB + k4 * 32 + bp_c16);
                uint32_t r4[4];
                ldsm4(r4, bufb + AT_KHO + bo);
                KH[nt][0] = r4[0]; KH[nt][1] = r4[1];
                KH[nt + 4][0] = r4[2]; KH[nt + 4][1] = r4[3];
                ldsm4(r4, bufb + AT_KLO + bo);
                KL[nt][0] = r4[0]; KL[nt][1] = r4[1];
                KL[nt + 4][0] = r4[2]; KL[nt + 4][1] = r4[3];
            }
#pragma unroll
            for (int nt = 0; nt < 8; nt++) {
                mma_h(S[nt], QA[k4], KH[nt]);
                mma_h(S[nt], QA[k4], KL[nt]);
            }
        }

        // ---- mask (diagonal tile) + online softmax (base 2) ----
        if (kt == qb) {
            int rbase = qbase + w * 16 + (lane >> 2);
#pragma unroll
            for (int nt = 0; nt < 8; nt++) {
                int cb = kt * 64 + nt * 8 + (lane & 3) * 2;
#pragma unroll
                for (int e = 0; e < 4; e++) {
                    int row = rbase + (e >> 1) * 8;
                    int col = cb + (e & 1);
                    if (col > row) S[nt][e] = -1e30f;
                }
            }
        }
#pragma unroll
        for (int h = 0; h < 2; h++) {
            float rm = -1e30f;
#pragma unroll
            for (int nt = 0; nt < 8; nt++)
                rm = fmaxf(rm, fmaxf(S[nt][2 * h], S[nt][2 * h + 1]));
            rm = qmax(rm);
            float mn = fmaxf(m_[h], rm);
            float sc = ex2(m_[h] - mn);
            m_[h] = mn;
            float rs = 0.f;
#pragma unroll
            for (int nt = 0; nt < 8; nt++) {
                float p0 = ex2(S[nt][2 * h] - mn);
                float p1 = ex2(S[nt][2 * h + 1] - mn);
                S[nt][2 * h] = p0; S[nt][2 * h + 1] = p1;
                rs += p0 + p1;
            }
            rs = qsum(rs);
            l_[h] = l_[h] * sc + rs;
#pragma unroll
            for (int nd = 0; nd < 8; nd++) {
                O[nd][2 * h]     *= sc;
                O[nd][2 * h + 1] *= sc;
            }
        }

        // ---- O += Ph·Vh + Ph·Vl  (fp16 2-term, P single) ----
#pragma unroll
        for (int k4 = 0; k4 < 4; k4++) {
            uint32_t Ph[4];
            Ph[0] = f2h2(S[2 * k4][0],     S[2 * k4][1]);
            Ph[1] = f2h2(S[2 * k4][2],     S[2 * k4][3]);
            Ph[2] = f2h2(S[2 * k4 + 1][0], S[2 * k4 + 1][1]);
            Ph[3] = f2h2(S[2 * k4 + 1][2], S[2 * k4 + 1][3]);
            uint32_t VH[8][2], VL[8][2];
#pragma unroll
            for (int nd = 0; nd < 4; nd++) {
                uint32_t vo = (uint32_t)((k4 * 16 + vp_row) * PADB + nd * 16 + vp_c16);
                uint32_t r4[4];
                ldsm4t(r4, bufb + AT_VHO + vo);
                VH[nd][0] = r4[0]; VH[nd][1] = r4[1];
                VH[nd + 4][0] = r4[2]; VH[nd + 4][1] = r4[3];
                ldsm4t(r4, bufb + AT_VLO + vo);
                VL[nd][0] = r4[0]; VL[nd][1] = r4[1];
                VL[nd + 4][0] = r4[2]; VL[nd + 4][1] = r4[3];
            }
#pragma unroll
            for (int nd = 0; nd < 8; nd++) {
                mma_h(O[nd], Ph, VH[nd]);
                mma_h(O[nd], Ph, VL[nd]);
            }
        }
        __syncthreads();
    }

    // ---- output ----
    if (entry < 0) {
        float inv0 = 1.f / l_[0];
        float inv1 = 1.f / l_[1];
        int row_a = qbase + w * 16 + (lane >> 2);
#pragma unroll
        for (int nd = 0; nd < 8; nd++) {
            int col = nd * 8 + (lane & 3) * 2;
            float2 v0 = make_float2(O[nd][0] * inv0, O[nd][1] * inv0);
            float2 v1 = make_float2(O[nd][2] * inv1, O[nd][3] * inv1);
            *(float2*)&out[((size_t)b * SEQ + row_a) * HEAD + col]     = v0;
            *(float2*)&out[((size_t)b * SEQ + row_a + 8) * HEAD + col] = v1;
        }
    } else {
        float* po = g_po[entry];
        int rloc = w * 16 + (lane >> 2);
#pragma unroll
        for (int h = 0; h < 2; h++) {
            int r = rloc + h * 8;
            if ((lane & 3) == 0) {
                g_pm[entry][r] = m_[h];
                g_pl[entry][r] = l_[h];
            }
#pragma unroll
            for (int nd = 0; nd < 8; nd++) {
                int col = nd * 8 + (lane & 3) * 2;
                *(float2*)&po[r * 64 + col] = make_float2(O[nd][2 * h], O[nd][2 * h + 1]);
            }
        }
    }
}

// ---------------------------------------------------------------------------
// Kernel 3: merge split-K partials (base-2 domain). Grid (16, 8) x 128 thr.
// ---------------------------------------------------------------------------
__global__ __launch_bounds__(128) void combine_kernel(float* __restrict__ out)
{
    const int qb = 16 + blockIdx.x;
    const int b  = blockIdx.y;
    const int e0 = ((b * 16 + blockIdx.x) << 1);
    const int e1 = e0 | 1;
    const int tid = threadIdx.x;
    const int row = tid >> 1;            // 0..63
    const int ch  = (tid & 1) * 32;      // column half

    float m0 = g_pm[e0][row], m1 = g_pm[e1][row];
    float l0 = g_pl[e0][row], l1 = g_pl[e1][row];
    float m = fmaxf(m0, m1);
    float f0 = ex2(m0 - m), f1 = ex2(m1 - m);
    float inv = 1.f / (l0 * f0 + l1 * f1);

    const float* p0 = &g_po[e0][row * 64 + ch];
    const float* p1 = &g_po[e1][row * 64 + ch];
    float* op = &out[((size_t)b * SEQ + qb * 64 + row) * HEAD + ch];
#pragma unroll
    for (int c4 = 0; c4 < 8; c4++) {
        float4 a = *(const float4*)&p0[c4 * 4];
        float4 d = *(const float4*)&p1[c4 * 4];
        float4 r;
        r.x = (a.x * f0 + d.x * f1) * inv;
        r.y = (a.y * f0 + d.y * f1) * inv;
        r.z = (a.z * f0 + d.z * f1) * inv;
        r.w = (a.w * f0 + d.w * f1) * inv;
        *(float4*)&op[c4 * 4] = r;
    }
}

// ---------------------------------------------------------------------------
extern "C" void kernel_launch(void* const* d_in, const int* in_sizes, int n_in,
                              void* d_out, int out_size)
{
    const float* x  = (const float*)d_in[0];
    const float* Wq = (const float*)d_in[1];
    const float* Wk = (const float*)d_in[2];
    const float* Wv = (const float*)d_in[3];
    float* out = (float*)d_out;

    cudaFuncSetAttribute(proj_kernel, cudaFuncAttributeMaxDynamicSharedMemorySize, PJ_SMEM);
    cudaFuncSetAttribute(attn_kernel, cudaFuncAttributeMaxDynamicSharedMemorySize, AT_SMEM);

    wprep_kernel<<<(192 * 1024 + 255) / 256, 256>>>(Wq, Wk, Wv);
    proj_kernel<<<128, 256, PJ_SMEM>>>(x);

    dim3 g2(48, BATCH);
    attn_kernel<<<g2, 128, AT_SMEM>>>(out);

    dim3 g3(16, BATCH);
    combine_kernel<<<g3, 128>>>(out);
}

// round 17
// speedup vs baseline: 1.0727x; 1.0727x over previous
#include <cuda_runtime.h>
#include <cuda_bf16.h>
#include <cuda_fp16.h>
#include <math.h>
#include <stdint.h>

#define BATCH 8
#define SEQ   2048
#define EMBED 1024
#define HEAD  64
#define MROWS (BATCH * SEQ)          // 16384

// Projected q,k,v in fp16. q: single (pre-scaled by log2(e)/32). k,v: hi/lo.
__device__ __half g_qh[MROWS * HEAD];
__device__ __half g_kh[MROWS * HEAD];
__device__ __half g_kl[MROWS * HEAD];
__device__ __half g_vh[MROWS * HEAD];
__device__ __half g_vl[MROWS * HEAD];

// W transposed (bf16 hi/lo; proj-internal): row = mat*64+n, col = k.
__device__ __nv_bfloat16 g_wth[192 * 1024];
__device__ __nv_bfloat16 g_wtl[192 * 1024];

#define QSCALE 0.045084220027780106f   // log2(e) / 32

// qb permutation: balances co-resident CTA pairs (x paired with (x+20)%32 on
// one SM via bid/bid+148 placement). Max pair sum (qb+1 units) = 36 vs 52 naive.
__constant__ int QB_PERM[32] = {
    31, 27, 23, 19,  2,  6, 10, 14,
    30, 26, 22, 18,  3,  7, 11, 15,
    29, 25, 21, 17,  0,  4,  8, 12,
    28, 24, 20, 16,  1,  5,  9, 13
};

// ---------------------------------------------------------------------------
// Helpers
// ---------------------------------------------------------------------------
__device__ __forceinline__ uint32_t smem_u32(const void* p) {
    uint32_t a;
    asm("{ .reg .u64 t; cvta.to.shared.u64 t, %1; cvt.u32.u64 %0, t; }" : "=r"(a) : "l"(p));
    return a;
}
__device__ __forceinline__ void ldsm4(uint32_t* r, uint32_t a) {
    asm volatile("ldmatrix.sync.aligned.m8n8.x4.shared.b16 {%0,%1,%2,%3}, [%4];"
        : "=r"(r[0]), "=r"(r[1]), "=r"(r[2]), "=r"(r[3]) : "r"(a));
}
__device__ __forceinline__ void ldsm2(uint32_t* r, uint32_t a) {
    asm volatile("ldmatrix.sync.aligned.m8n8.x2.shared.b16 {%0,%1}, [%2];"
        : "=r"(r[0]), "=r"(r[1]) : "r"(a));
}
__device__ __forceinline__ void ldsm4t(uint32_t* r, uint32_t a) {
    asm volatile("ldmatrix.sync.aligned.m8n8.x4.trans.shared.b16 {%0,%1,%2,%3}, [%4];"
        : "=r"(r[0]), "=r"(r[1]), "=r"(r[2]), "=r"(r[3]) : "r"(a));
}
__device__ __forceinline__ void mma_bf(float* c, const uint32_t* a, const uint32_t* b) {
    asm volatile("mma.sync.aligned.m16n8k16.row.col.f32.bf16.bf16.f32 "
        "{%0,%1,%2,%3}, {%4,%5,%6,%7}, {%8,%9}, {%0,%1,%2,%3};"
        : "+f"(c[0]), "+f"(c[1]), "+f"(c[2]), "+f"(c[3])
        : "r"(a[0]), "r"(a[1]), "r"(a[2]), "r"(a[3]), "r"(b[0]), "r"(b[1]));
}
__device__ __forceinline__ void mma_h(float* c, const uint32_t* a, const uint32_t* b) {
    asm volatile("mma.sync.aligned.m16n8k16.row.col.f32.f16.f16.f32 "
        "{%0,%1,%2,%3}, {%4,%5,%6,%7}, {%8,%9}, {%0,%1,%2,%3};"
        : "+f"(c[0]), "+f"(c[1]), "+f"(c[2]), "+f"(c[3])
        : "r"(a[0]), "r"(a[1]), "r"(a[2]), "r"(a[3]), "r"(b[0]), "r"(b[1]));
}
__device__ __forceinline__ uint32_t f2bf2(float lo, float hi) {
    uint32_t r;
    asm("cvt.rn.bf16x2.f32 %0, %1, %2;" : "=r"(r) : "f"(hi), "f"(lo));
    return r;
}
__device__ __forceinline__ uint32_t f2h2(float lo, float hi) {
    uint32_t r;
    asm("cvt.rn.f16x2.f32 %0, %1, %2;" : "=r"(r) : "f"(hi), "f"(lo));
    return r;
}
__device__ __forceinline__ void split2(float v, float& hf, float& lf) {
    __nv_bfloat16 h = __float2bfloat16_rn(v);
    hf = __bfloat162float(h);
    lf = v - hf;
}
__device__ __forceinline__ void splitpackh(float v0, float v1, uint32_t& ph, uint32_t& pl) {
    __half h0 = __float2half_rn(v0), h1 = __float2half_rn(v1);
    float l0 = v0 - __half2float(h0), l1 = v1 - __half2float(h1);
    ph = (uint32_t)__half_as_ushort(h0) | ((uint32_t)__half_as_ushort(h1) << 16);
    pl = f2h2(l0, l1);
}
__device__ __forceinline__ float ex2(float x) {
    float r; asm("ex2.approx.ftz.f32 %0, %1;" : "=f"(r) : "f"(x)); return r;
}
__device__ __forceinline__ float qmax(float v) {
    v = fmaxf(v, __shfl_xor_sync(0xffffffffu, v, 1));
    v = fmaxf(v, __shfl_xor_sync(0xffffffffu, v, 2));
    return v;
}
__device__ __forceinline__ float qsum(float v) {
    v += __shfl_xor_sync(0xffffffffu, v, 1);
    v += __shfl_xor_sync(0xffffffffu, v, 2);
    return v;
}
__device__ __forceinline__ void cp16(uint32_t dst, const void* src) {
    asm volatile("cp.async.cg.shared.global [%0], [%1], 16;" :: "r"(dst), "l"(src));
}
#define CP_COMMIT() asm volatile("cp.async.commit_group;" ::: "memory")
#define CP_WAIT(n)  asm volatile("cp.async.wait_group %0;" :: "n"(n) : "memory")

#define PADB 144   // padded row pitch (bytes)

// ---------------------------------------------------------------------------
// Kernel 0: W prep (bf16 hi/lo)
// ---------------------------------------------------------------------------
__global__ __launch_bounds__(256) void wprep_kernel(
    const float* __restrict__ Wq,
    const float* __restrict__ Wk,
    const float* __restrict__ Wv)
{
    int i = blockIdx.x * 256 + threadIdx.x;
    if (i >= 192 * 1024) return;
    int row = i >> 10;
    int k   = i & 1023;
    int mat = row >> 6;
    int n   = row & 63;
    const float* W = (mat == 0) ? Wq : ((mat == 1) ? Wk : Wv);
    float v = W[(size_t)k * HEAD + n];
    float hf, lf; split2(v, hf, lf);
    g_wth[i] = __float2bfloat16_rn(hf);
    g_wtl[i] = __float2bfloat16_rn(lf);
}

// ---------------------------------------------------------------------------
// Kernel 1: QKV projection (3-term bf16 internally; fp16 outputs)
// ---------------------------------------------------------------------------
#define PJ_XH  0
#define PJ_XL  18432
#define PJ_WH  36864
#define PJ_WL  64512
#define PJ_SMEM 92160

__global__ __launch_bounds__(256) void proj_kernel(const float* __restrict__ x)
{
    extern __shared__ char smem[];
    const uint32_t sb = smem_u32(smem);
    const int tid  = threadIdx.x;
    const int w    = tid >> 5;
    const int lane = tid & 31;
    const int r0   = (w >> 1) * 32;
    const int c0   = (w & 1) * 96;
    const int row0 = blockIdx.x * 128;

    float C[2][12][4];
#pragma unroll
    for (int mt = 0; mt < 2; mt++)
#pragma unroll
        for (int nt = 0; nt < 12; nt++)
#pragma unroll
            for (int e = 0; e < 4; e++) C[mt][nt][e] = 0.f;

    const int a_row = (lane & 7) + ((lane >> 3) & 1) * 8;
    const int a_c16 = ((lane >> 4) & 1) * 16;
    const int b_row = lane & 7;
    const int b_c16 = ((lane >> 3) & 1) * 16;

    for (int c = 0; c < 16; c++) {
        const int k0 = c * 64;
        for (int i = tid; i < 2048; i += 256) {
            int r = i >> 4, c4 = i & 15;
            float4 v = *(const float4*)&x[(size_t)(row0 + r) * EMBED + k0 + c4 * 4];
            float h0, l0, h1, l1, h2, l2, h3, l3;
            split2(v.x, h0, l0); split2(v.y, h1, l1);
            split2(v.z, h2, l2); split2(v.w, h3, l3);
            int off = r * PADB + c4 * 8;
            *(uint32_t*)(smem + PJ_XH + off)     = f2bf2(h0, h1);
            *(uint32_t*)(smem + PJ_XH + off + 4) = f2bf2(h2, h3);
            *(uint32_t*)(smem + PJ_XL + off)     = f2bf2(l0, l1);
            *(uint32_t*)(smem + PJ_XL + off + 4) = f2bf2(l2, l3);
        }
        for (int i = tid; i < 1536; i += 256) {
            int row = i >> 3, d8 = i & 7;
            size_t src = ((size_t)row * 1024 + k0) / 8 + d8;
            int off = row * PADB + d8 * 16;
            *(uint4*)(smem + PJ_WH + off) = ((const uint4*)g_wth)[src];
            *(uint4*)(smem + PJ_WL + off) = ((const uint4*)g_wtl)[src];
        }
        __syncthreads();

#pragma unroll
        for (int kt = 0; kt < 4; kt++) {
            uint32_t Ah[2][4], Al[2][4];
#pragma unroll
            for (int mt = 0; mt < 2; mt++) {
                uint32_t ao = (uint32_t)((r0 + mt * 16 + a_row) * PADB + kt * 32 + a_c16);
                ldsm4(Ah[mt], sb + PJ_XH + ao);
                ldsm4(Al[mt], sb + PJ_XL + ao);
            }
#pragma unroll
            for (int nt = 0; nt < 12; nt++) {
                uint32_t bo = (uint32_t)((c0 + nt * 8 + b_row) * PADB + kt * 32 + b_c16);
                uint32_t Bh[2], Bl[2];
                ldsm2(Bh, sb + PJ_WH + bo);
                ldsm2(Bl, sb + PJ_WL + bo);
#pragma unroll
                for (int mt = 0; mt < 2; mt++) {
                    mma_bf(C[mt][nt], Ah[mt], Bh);
                    mma_bf(C[mt][nt], Ah[mt], Bl);
                    mma_bf(C[mt][nt], Al[mt], Bh);
                }
            }
        }
        __syncthreads();
    }

#pragma unroll
    for (int mt = 0; mt < 2; mt++) {
#pragma unroll
        for (int nt = 0; nt < 12; nt++) {
            int col = c0 + nt * 8 + (lane & 3) * 2;
            int mat = col >> 6;
            int cc  = col & 63;
            int row_a = row0 + r0 + mt * 16 + (lane >> 2);
#pragma unroll
            for (int h = 0; h < 2; h++) {
                int row = row_a + h * 8;
                float v0 = C[mt][nt][2 * h], v1 = C[mt][nt][2 * h + 1];
                if (mat == 0) {
                    *(uint32_t*)&g_qh[(size_t)row * HEAD + cc] = f2h2(v0 * QSCALE, v1 * QSCALE);
                } else {
                    __half* gh = (mat == 1) ? g_kh : g_vh;
                    __half* gl = (mat == 1) ? g_kl : g_vl;
                    uint32_t ph, pl;
                    splitpackh(v0, v1, ph, pl);
                    *(uint32_t*)&gh[(size_t)row * HEAD + cc] = ph;
                    *(uint32_t*)&gl[(size_t)row * HEAD + cc] = pl;
                }
            }
        }
    }
}

// ---------------------------------------------------------------------------
// Kernel 2: causal flash attention, fp16 2-term, single wave (256 CTAs),
// pair-balanced qb permutation. CTA = 128 threads, 64 q rows. Grid (32, 8).
// cp.async double-buffered K/V.
// ---------------------------------------------------------------------------
#define AT_QH   0
#define AT_BUF0 9216
#define AT_BUF1 46080
#define AT_KHO  0
#define AT_KLO  9216
#define AT_VHO  18432
#define AT_VLO  27648
#define AT_SMEM 82944

__global__ __launch_bounds__(128) void attn_kernel(float* __restrict__ out)
{
    extern __shared__ char smem[];
    const uint32_t sb = smem_u32(smem);
    const int tid  = threadIdx.x;
    const int w    = tid >> 5;
    const int lane = tid & 31;
    const int b    = blockIdx.y;
    const int qb   = QB_PERM[blockIdx.x];
    const int qbase = qb * 64;
    const int ntiles = qb + 1;

    auto issue_tile = [&](int kt, int buf) {
        const size_t gb = ((size_t)b * SEQ + kt * 64) * HEAD;
        const uint32_t bufb = sb + (buf ? AT_BUF1 : AT_BUF0);
#pragma unroll
        for (int i = tid; i < 2048; i += 128) {
            int arr = i >> 9, rem = i & 511;
            int r = rem >> 3, d8 = rem & 7;
            const __half* src =
                (arr == 0) ? g_kh : ((arr == 1) ? g_kl : ((arr == 2) ? g_vh : g_vl));
            int aoff = (arr == 0) ? AT_KHO : ((arr == 1) ? AT_KLO : ((arr == 2) ? AT_VHO : AT_VLO));
            cp16(bufb + aoff + r * PADB + d8 * 16, src + gb + (size_t)r * HEAD + d8 * 8);
        }
        CP_COMMIT();
    };

    issue_tile(0, 0);

    // Q tile (64 x 64 fp16) -> smem -> hoisted register fragments
    {
        const uint4* qh = (const uint4*)(g_qh + ((size_t)b * SEQ + qbase) * HEAD);
        for (int i = tid; i < 512; i += 128) {
            int r = i >> 3, d8 = i & 7;
            *(uint4*)(smem + AT_QH + r * PADB + d8 * 16) = qh[i];
        }
    }
    __syncthreads();

    const int a_row = (lane & 7) + ((lane >> 3) & 1) * 8;
    const int a_c16 = ((lane >> 4) & 1) * 16;
    uint32_t QA[4][4];
#pragma unroll
    for (int k4 = 0; k4 < 4; k4++)
        ldsm4(QA[k4], sb + AT_QH + (uint32_t)((w * 16 + a_row) * PADB + k4 * 32 + a_c16));

    float O[8][4];
    float m_[2], l_[2];
#pragma unroll
    for (int nd = 0; nd < 8; nd++)
#pragma unroll
        for (int e = 0; e < 4; e++) O[nd][e] = 0.f;
    m_[0] = m_[1] = -1e30f;
    l_[0] = l_[1] = 0.f;

    const int bp_row = (lane & 7) + ((lane >> 4) & 1) * 32;
    const int bp_c16 = ((lane >> 3) & 1) * 16;
    const int vp_row = lane & 15;
    const int vp_c16 = ((lane >> 4) & 1) * 64;

    for (int kt = 0; kt < ntiles; kt++) {
        const int cur = kt & 1;
        if (kt + 1 < ntiles) { issue_tile(kt + 1, 1 - cur); CP_WAIT(1); }
        else                 { CP_WAIT(0); }
        __syncthreads();

        const uint32_t bufb = sb + (cur ? AT_BUF1 : AT_BUF0);

        // ---- S = Qh·Kh + Qh·Kl  (fp16 2-term) ----
        float S[8][4];
#pragma unroll
        for (int nt = 0; nt < 8; nt++)
#pragma unroll
            for (int e = 0; e < 4; e++) S[nt][e] = 0.f;

#pragma unroll
        for (int k4 = 0; k4 < 4; k4++) {
            uint32_t KH[8][2], KL[8][2];
#pragma unroll
            for (int nt = 0; nt < 4; nt++) {
                uint32_t bo = (uint32_t)((nt * 8 + bp_row) * PADB + k4 * 32 + bp_c16);
                uint32_t r4[4];
                ldsm4(r4, bufb + AT_KHO + bo);
                KH[nt][0] = r4[0]; KH[nt][1] = r4[1];
                KH[nt + 4][0] = r4[2]; KH[nt + 4][1] = r4[3];
                ldsm4(r4, bufb + AT_KLO + bo);
                KL[nt][0] = r4[0]; KL[nt][1] = r4[1];
                KL[nt + 4][0] = r4[2]; KL[nt + 4][1] = r4[3];
            }
#pragma unroll
            for (int nt = 0; nt < 8; nt++) {
                mma_h(S[nt], QA[k4], KH[nt]);
                mma_h(S[nt], QA[k4], KL[nt]);
            }
        }

        // ---- mask (diagonal tile) + online softmax (base 2) ----
        if (kt == qb) {
            int rbase = qbase + w * 16 + (lane >> 2);
#pragma unroll
            for (int nt = 0; nt < 8; nt++) {
                int cb = kt * 64 + nt * 8 + (lane & 3) * 2;
#pragma unroll
                for (int e = 0; e < 4; e++) {
                    int row = rbase + (e >> 1) * 8;
                    int col = cb + (e & 1);
                    if (col > row) S[nt][e] = -1e30f;
                }
            }
        }
#pragma unroll
        for (int h = 0; h < 2; h++) {
            float rm = -1e30f;
#pragma unroll
            for (int nt = 0; nt < 8; nt++)
                rm = fmaxf(rm, fmaxf(S[nt][2 * h], S[nt][2 * h + 1]));
            rm = qmax(rm);
            float mn = fmaxf(m_[h], rm);
            float sc = ex2(m_[h] - mn);
            m_[h] = mn;
            float rs = 0.f;
#pragma unroll
            for (int nt = 0; nt < 8; nt++) {
                float p0 = ex2(S[nt][2 * h] - mn);
                float p1 = ex2(S[nt][2 * h + 1] - mn);
                S[nt][2 * h] = p0; S[nt][2 * h + 1] = p1;
                rs += p0 + p1;
            }
            rs = qsum(rs);
            l_[h] = l_[h] * sc + rs;
#pragma unroll
            for (int nd = 0; nd < 8; nd++) {
                O[nd][2 * h]     *= sc;
                O[nd][2 * h + 1] *= sc;
            }
        }

        // ---- O += Ph·Vh + Ph·Vl  (fp16 2-term, P single) ----
#pragma unroll
        for (int k4 = 0; k4 < 4; k4++) {
            uint32_t Ph[4];
            Ph[0] = f2h2(S[2 * k4][0],     S[2 * k4][1]);
            Ph[1] = f2h2(S[2 * k4][2],     S[2 * k4][3]);
            Ph[2] = f2h2(S[2 * k4 + 1][0], S[2 * k4 + 1][1]);
            Ph[3] = f2h2(S[2 * k4 + 1][2], S[2 * k4 + 1][3]);
            uint32_t VH[8][2], VL[8][2];
#pragma unroll
            for (int nd = 0; nd < 4; nd++) {
                uint32_t vo = (uint32_t)((k4 * 16 + vp_row) * PADB + nd * 16 + vp_c16);
                uint32_t r4[4];
                ldsm4t(r4, bufb + AT_VHO + vo);
                VH[nd][0] = r4[0]; VH[nd][1] = r4[1];
                VH[nd + 4][0] = r4[2]; VH[nd + 4][1] = r4[3];
                ldsm4t(r4, bufb + AT_VLO + vo);
                VL[nd][0] = r4[0]; VL[nd][1] = r4[1];
                VL[nd + 4][0] = r4[2]; VL[nd + 4][1] = r4[3];
            }
#pragma unroll
            for (int nd = 0; nd < 8; nd++) {
                mma_h(O[nd], Ph, VH[nd]);
                mma_h(O[nd], Ph, VL[nd]);
            }
        }
        __syncthreads();
    }

    // ---- store ----
    float inv0 = 1.f / l_[0];
    float inv1 = 1.f / l_[1];
    int row_a = qbase + w * 16 + (lane >> 2);
#pragma unroll
    for (int nd = 0; nd < 8; nd++) {
        int col = nd * 8 + (lane & 3) * 2;
        float2 v0 = make_float2(O[nd][0] * inv0, O[nd][1] * inv0);
        float2 v1 = make_float2(O[nd][2] * inv1, O[nd][3] * inv1);
        *(float2*)&out[((size_t)b * SEQ + row_a) * HEAD + col]     = v0;
        *(float2*)&out[((size_t)b * SEQ + row_a + 8) * HEAD + col] = v1;
    }
}

// ---------------------------------------------------------------------------
extern "C" void kernel_launch(void* const* d_in, const int* in_sizes, int n_in,
                              void* d_out, int out_size)
{
    const float* x  = (const float*)d_in[0];
    const float* Wq = (const float*)d_in[1];
    const float* Wk = (const float*)d_in[2];
    const float* Wv = (const float*)d_in[3];
    float* out = (float*)d_out;

    cudaFuncSetAttribute(proj_kernel, cudaFuncAttributeMaxDynamicSharedMemorySize, PJ_SMEM);
    cudaFuncSetAttribute(attn_kernel, cudaFuncAttributeMaxDynamicSharedMemorySize, AT_SMEM);

    wprep_kernel<<<(192 * 1024 + 255) / 256, 256>>>(Wq, Wk, Wv);
    proj_kernel<<<128, 256, PJ_SMEM>>>(x);

    dim3 g2(32, BATCH);
    attn_kernel<<<g2, 128, AT_SMEM>>>(out);
}